// round 9
// baseline (speedup 1.0000x reference)
#include <cuda_runtime.h>

// WaveletNet: 4 lifting steps with length-1 filters == elementwise 2x2 linear map.
// Evens half of each output row: m00*e + m01*o ; details half: m10*e + m11*o,
// with M = prod_{k=3..0} [[1-u_k p_k, u_k], [-p_k, 1]].
// R9: R4 structure (2 octs/thread, 4x front-batched LDG.128, 4x STG.128) with
// DEFAULT write-back stores. Under graph replay, dirty output lines stay in the
// 126MB L2 and are overwritten in place next replay -> write stream largely
// never reaches DRAM (untested cell of the policy matrix; all prior rounds
// used cs/wt streaming stores that force writes to DRAM).

#define L_FULL 65536
#define L_HALF 32768
#define B_DIM  256
#define OCTS_PER_ROW (L_FULL / 8)          // 8192 (one oct = 8 floats = 4 pairs)
#define OCT_SHIFT 13
#define OCT_MASK  (OCTS_PER_ROW - 1)
#define N_OCTS ((long long)B_DIM * OCTS_PER_ROW)   // 2,097,152
#define Z_ELEMS ((long long)B_DIM * L_FULL)        // 16,777,216
#define THREADS 256
#define OCTS_PER_THREAD 2
#define OCTS_PER_BLOCK (THREADS * OCTS_PER_THREAD) // 512

__global__ void __launch_bounds__(THREADS)
wavelet_fused_kernel(const float4* __restrict__ x4,
                     const float* __restrict__ P,
                     const float* __restrict__ U,
                     float* __restrict__ out,
                     long long out_size)
{
    // Compose the 4 lifting steps into one 2x2 matrix (coeffs L1-cached, cheap).
    float m00 = 1.f, m01 = 0.f, m10 = 0.f, m11 = 1.f;
#pragma unroll
    for (int k = 0; k < 4; k++) {
        float p = __ldg(&P[k]);
        float u = __ldg(&U[k]);
        float a00 = 1.f - u * p, a01 = u;
        float a10 = -p,          a11 = 1.f;
        float n00 = a00 * m00 + a01 * m10;
        float n01 = a00 * m01 + a01 * m11;
        float n10 = a10 * m00 + a11 * m10;
        float n11 = a10 * m01 + a11 * m11;
        m00 = n00; m01 = n01; m10 = n10; m11 = n11;
    }

    // Two octs per thread, blockDim apart (both fully coalesced at warp level).
    long long g0 = (long long)blockIdx.x * OCTS_PER_BLOCK + threadIdx.x;
    long long g1 = g0 + THREADS;

    // Front-batched loads: 4 independent LDG.128 before any arithmetic.
    const float4* s0 = x4 + 2 * g0;
    const float4* s1 = x4 + 2 * g1;
    float4 a0 = __ldg(s0);
    float4 a1 = __ldg(s0 + 1);
    float4 b0 = __ldg(s1);
    float4 b1 = __ldg(s1 + 1);

    float4 ev0, od0, ev1, od1;
    ev0.x = m00 * a0.x + m01 * a0.y;  od0.x = m10 * a0.x + m11 * a0.y;
    ev0.y = m00 * a0.z + m01 * a0.w;  od0.y = m10 * a0.z + m11 * a0.w;
    ev0.z = m00 * a1.x + m01 * a1.y;  od0.z = m10 * a1.x + m11 * a1.y;
    ev0.w = m00 * a1.z + m01 * a1.w;  od0.w = m10 * a1.z + m11 * a1.w;

    ev1.x = m00 * b0.x + m01 * b0.y;  od1.x = m10 * b0.x + m11 * b0.y;
    ev1.y = m00 * b0.z + m01 * b0.w;  od1.y = m10 * b0.z + m11 * b0.w;
    ev1.z = m00 * b1.x + m01 * b1.y;  od1.z = m10 * b1.x + m11 * b1.y;
    ev1.w = m00 * b1.z + m01 * b1.w;  od1.w = m10 * b1.z + m11 * b1.w;

    {
        long long b = g0 >> OCT_SHIFT;
        long long q = g0 & OCT_MASK;
        float* row = out + b * (long long)L_FULL;
        long long i = 4 * q;
        *reinterpret_cast<float4*>(row + i)          = ev0;  // default write-back
        *reinterpret_cast<float4*>(row + L_HALF + i) = od0;
    }
    {
        long long b = g1 >> OCT_SHIFT;
        long long q = g1 & OCT_MASK;
        float* row = out + b * (long long)L_FULL;
        long long i = 4 * q;
        *reinterpret_cast<float4*>(row + i)          = ev1;
        *reinterpret_cast<float4*>(row + L_HALF + i) = od1;
    }

    // log_det (and any padding beyond z) = 0
    if (g0 == 0) {
        for (long long i = Z_ELEMS; i < out_size; i++) out[i] = 0.0f;
    }
}

extern "C" void kernel_launch(void* const* d_in, const int* in_sizes, int n_in,
                              void* d_out, int out_size)
{
    const float4* x4 = (const float4*)d_in[0];
    const float*  P  = (const float*)d_in[1];
    const float*  U  = (const float*)d_in[2];
    float* out = (float*)d_out;

    const int blocks = (int)(N_OCTS / OCTS_PER_BLOCK);  // 4096, exact cover
    wavelet_fused_kernel<<<blocks, THREADS>>>(x4, P, U, out, (long long)out_size);
}

// round 10
// speedup vs baseline: 1.0843x; 1.0843x over previous
#include <cuda_runtime.h>

// WaveletNet: 4 lifting steps with length-1 filters == elementwise 2x2 linear map.
// Evens half of each output row: m00*e + m01*o ; details half: m10*e + m11*o,
// with M = prod_{k=3..0} [[1-u_k p_k, u_k], [-p_k, 1]].
//
// FINAL (R4 champion, re-confirmed R8): 2 octs/thread, 4x front-batched LDG.128
// (default-cached), 4x STG.128 evict-first (.cs) stores.
//
// Roofline verdict after 9 structural variants (MLP 1/2/4; 64/128/256-bit ops;
// load policies ca/nc/cg/cs; store policies cs/wt/wb): kernel time pinned at
// 18.0-19.3us = 128MB compulsory R+W / ~7.1 TB/s achieved mixed-stream HBM3e
// bandwidth. No SM-side counter exceeds 60% because the binding constraint is
// the composite read+write DRAM stream. This is the memory floor.

#define L_FULL 65536
#define L_HALF 32768
#define B_DIM  256
#define OCTS_PER_ROW (L_FULL / 8)          // 8192 (one oct = 8 floats = 4 pairs)
#define OCT_SHIFT 13
#define OCT_MASK  (OCTS_PER_ROW - 1)
#define N_OCTS ((long long)B_DIM * OCTS_PER_ROW)   // 2,097,152
#define Z_ELEMS ((long long)B_DIM * L_FULL)        // 16,777,216
#define THREADS 256
#define OCTS_PER_THREAD 2
#define OCTS_PER_BLOCK (THREADS * OCTS_PER_THREAD) // 512

__global__ void __launch_bounds__(THREADS)
wavelet_fused_kernel(const float4* __restrict__ x4,
                     const float* __restrict__ P,
                     const float* __restrict__ U,
                     float* __restrict__ out,
                     long long out_size)
{
    // Compose the 4 lifting steps into one 2x2 matrix (coeffs L1-cached, cheap).
    float m00 = 1.f, m01 = 0.f, m10 = 0.f, m11 = 1.f;
#pragma unroll
    for (int k = 0; k < 4; k++) {
        float p = __ldg(&P[k]);
        float u = __ldg(&U[k]);
        float a00 = 1.f - u * p, a01 = u;
        float a10 = -p,          a11 = 1.f;
        float n00 = a00 * m00 + a01 * m10;
        float n01 = a00 * m01 + a01 * m11;
        float n10 = a10 * m00 + a11 * m10;
        float n11 = a10 * m01 + a11 * m11;
        m00 = n00; m01 = n01; m10 = n10; m11 = n11;
    }

    // Two octs per thread, blockDim apart (both fully coalesced at warp level).
    long long g0 = (long long)blockIdx.x * OCTS_PER_BLOCK + threadIdx.x;
    long long g1 = g0 + THREADS;

    // Front-batched loads: 4 independent LDG.128 before any arithmetic.
    const float4* s0 = x4 + 2 * g0;
    const float4* s1 = x4 + 2 * g1;
    float4 a0 = __ldg(s0);
    float4 a1 = __ldg(s0 + 1);
    float4 b0 = __ldg(s1);
    float4 b1 = __ldg(s1 + 1);

    float4 ev0, od0, ev1, od1;
    ev0.x = m00 * a0.x + m01 * a0.y;  od0.x = m10 * a0.x + m11 * a0.y;
    ev0.y = m00 * a0.z + m01 * a0.w;  od0.y = m10 * a0.z + m11 * a0.w;
    ev0.z = m00 * a1.x + m01 * a1.y;  od0.z = m10 * a1.x + m11 * a1.y;
    ev0.w = m00 * a1.z + m01 * a1.w;  od0.w = m10 * a1.z + m11 * a1.w;

    ev1.x = m00 * b0.x + m01 * b0.y;  od1.x = m10 * b0.x + m11 * b0.y;
    ev1.y = m00 * b0.z + m01 * b0.w;  od1.y = m10 * b0.z + m11 * b0.w;
    ev1.z = m00 * b1.x + m01 * b1.y;  od1.z = m10 * b1.x + m11 * b1.y;
    ev1.w = m00 * b1.z + m01 * b1.w;  od1.w = m10 * b1.z + m11 * b1.w;

    {
        long long b = g0 >> OCT_SHIFT;
        long long q = g0 & OCT_MASK;
        float* row = out + b * (long long)L_FULL;
        long long i = 4 * q;
        __stcs(reinterpret_cast<float4*>(row + i), ev0);
        __stcs(reinterpret_cast<float4*>(row + L_HALF + i), od0);
    }
    {
        long long b = g1 >> OCT_SHIFT;
        long long q = g1 & OCT_MASK;
        float* row = out + b * (long long)L_FULL;
        long long i = 4 * q;
        __stcs(reinterpret_cast<float4*>(row + i), ev1);
        __stcs(reinterpret_cast<float4*>(row + L_HALF + i), od1);
    }

    // log_det (and any padding beyond z) = 0
    if (g0 == 0) {
        for (long long i = Z_ELEMS; i < out_size; i++) out[i] = 0.0f;
    }
}

extern "C" void kernel_launch(void* const* d_in, const int* in_sizes, int n_in,
                              void* d_out, int out_size)
{
    const float4* x4 = (const float4*)d_in[0];
    const float*  P  = (const float*)d_in[1];
    const float*  U  = (const float*)d_in[2];
    float* out = (float*)d_out;

    const int blocks = (int)(N_OCTS / OCTS_PER_BLOCK);  // 4096, exact cover
    wavelet_fused_kernel<<<blocks, THREADS>>>(x4, P, U, out, (long long)out_size);
}

// round 11
// speedup vs baseline: 1.2183x; 1.1235x over previous
#include <cuda_runtime.h>

// WaveletNet: 4 lifting steps with length-1 filters == elementwise 2x2 linear map.
// Evens half of each output row: m00*e + m01*o ; details half: m10*e + m11*o,
// with M = prod_{k=3..0} [[1-u_k p_k, u_k], [-p_k, 1]].
// R11: persistent single-wave grid-stride (888 CTAs = 148 SM x 6 resident),
// champion's memory ops (front-batched LDG.128 x2, .cs STG.128 x2 per iter).
// Rationale: eliminate (n_waves-1) wave transitions + per-wave memory ramp.

#define L_FULL 65536
#define L_HALF 32768
#define B_DIM  256
#define OCTS_PER_ROW (L_FULL / 8)          // 8192 (one oct = 8 floats = 4 pairs)
#define OCT_SHIFT 13
#define OCT_MASK  (OCTS_PER_ROW - 1)
#define N_OCTS ((long long)B_DIM * OCTS_PER_ROW)   // 2,097,152
#define Z_ELEMS ((long long)B_DIM * L_FULL)        // 16,777,216
#define THREADS 256
#define GRID_CTAS 888                               // 148 SMs * 6 CTAs (8 warps each)

__global__ void __launch_bounds__(THREADS)
wavelet_fused_kernel(const float4* __restrict__ x4,
                     const float* __restrict__ P,
                     const float* __restrict__ U,
                     float* __restrict__ out,
                     long long out_size)
{
    // Compose the 4 lifting steps into one 2x2 matrix (coeffs L1-cached, cheap).
    float m00 = 1.f, m01 = 0.f, m10 = 0.f, m11 = 1.f;
#pragma unroll
    for (int k = 0; k < 4; k++) {
        float p = __ldg(&P[k]);
        float u = __ldg(&U[k]);
        float a00 = 1.f - u * p, a01 = u;
        float a10 = -p,          a11 = 1.f;
        float n00 = a00 * m00 + a01 * m10;
        float n01 = a00 * m01 + a01 * m11;
        float n10 = a10 * m00 + a11 * m10;
        float n11 = a10 * m01 + a11 * m11;
        m00 = n00; m01 = n01; m10 = n10; m11 = n11;
    }

    const long long stride = (long long)GRID_CTAS * THREADS;  // octs per sweep step
    long long g = (long long)blockIdx.x * THREADS + threadIdx.x;

    // Grid-stride over oct pairs: each iteration handles octs g and g+stride
    // (both warp-coalesced). Persistent CTAs keep LSU pipelines in steady state.
    for (; g + stride < N_OCTS; g += 2 * stride) {
        long long g1 = g + stride;

        // Front-batched loads: 4 independent LDG.128 before any arithmetic.
        const float4* s0 = x4 + 2 * g;
        const float4* s1 = x4 + 2 * g1;
        float4 a0 = __ldg(s0);
        float4 a1 = __ldg(s0 + 1);
        float4 b0 = __ldg(s1);
        float4 b1 = __ldg(s1 + 1);

        float4 ev0, od0, ev1, od1;
        ev0.x = m00 * a0.x + m01 * a0.y;  od0.x = m10 * a0.x + m11 * a0.y;
        ev0.y = m00 * a0.z + m01 * a0.w;  od0.y = m10 * a0.z + m11 * a0.w;
        ev0.z = m00 * a1.x + m01 * a1.y;  od0.z = m10 * a1.x + m11 * a1.y;
        ev0.w = m00 * a1.z + m01 * a1.w;  od0.w = m10 * a1.z + m11 * a1.w;

        ev1.x = m00 * b0.x + m01 * b0.y;  od1.x = m10 * b0.x + m11 * b0.y;
        ev1.y = m00 * b0.z + m01 * b0.w;  od1.y = m10 * b0.z + m11 * b0.w;
        ev1.z = m00 * b1.x + m01 * b1.y;  od1.z = m10 * b1.x + m11 * b1.y;
        ev1.w = m00 * b1.z + m01 * b1.w;  od1.w = m10 * b1.z + m11 * b1.w;

        {
            long long b = g >> OCT_SHIFT;
            long long q = g & OCT_MASK;
            float* row = out + b * (long long)L_FULL;
            long long i = 4 * q;
            __stcs(reinterpret_cast<float4*>(row + i), ev0);
            __stcs(reinterpret_cast<float4*>(row + L_HALF + i), od0);
        }
        {
            long long b = g1 >> OCT_SHIFT;
            long long q = g1 & OCT_MASK;
            float* row = out + b * (long long)L_FULL;
            long long i = 4 * q;
            __stcs(reinterpret_cast<float4*>(row + i), ev1);
            __stcs(reinterpret_cast<float4*>(row + L_HALF + i), od1);
        }
    }

    // Remainder: single-oct iterations.
    for (; g < N_OCTS; g += stride) {
        const float4* s0 = x4 + 2 * g;
        float4 a0 = __ldg(s0);
        float4 a1 = __ldg(s0 + 1);

        float4 ev0, od0;
        ev0.x = m00 * a0.x + m01 * a0.y;  od0.x = m10 * a0.x + m11 * a0.y;
        ev0.y = m00 * a0.z + m01 * a0.w;  od0.y = m10 * a0.z + m11 * a0.w;
        ev0.z = m00 * a1.x + m01 * a1.y;  od0.z = m10 * a1.x + m11 * a1.y;
        ev0.w = m00 * a1.z + m01 * a1.w;  od0.w = m10 * a1.z + m11 * a1.w;

        long long b = g >> OCT_SHIFT;
        long long q = g & OCT_MASK;
        float* row = out + b * (long long)L_FULL;
        long long i = 4 * q;
        __stcs(reinterpret_cast<float4*>(row + i), ev0);
        __stcs(reinterpret_cast<float4*>(row + L_HALF + i), od0);
    }

    // log_det (and any padding beyond z) = 0
    if (blockIdx.x == 0 && threadIdx.x == 0) {
        for (long long i = Z_ELEMS; i < out_size; i++) out[i] = 0.0f;
    }
}

extern "C" void kernel_launch(void* const* d_in, const int* in_sizes, int n_in,
                              void* d_out, int out_size)
{
    const float4* x4 = (const float4*)d_in[0];
    const float*  P  = (const float*)d_in[1];
    const float*  U  = (const float*)d_in[2];
    float* out = (float*)d_out;

    wavelet_fused_kernel<<<GRID_CTAS, THREADS>>>(x4, P, U, out, (long long)out_size);
}